// round 1
// baseline (speedup 1.0000x reference)
#include <cuda_runtime.h>
#include <math.h>

// Shapes are fixed by the benchmark.
#define B_ 256
#define T_ 512
#define D_ 256
#define A_ 50
#define AH 25      // A processed in two halves of 25 (regs + static smem budget)
#define ROWS 128   // rows (b*t) per block in score kernel
#define DC 16      // d-chunk staged per tile

// Scratch for per-row raw scores (pre-exp). 512 KB, static device global (allowed).
__device__ float g_scores[B_ * T_];

// ---------------------------------------------------------------------------
// Kernel 1: score[r] = sum_a tanh( (x_row . W[:,a]) + b[a] ) * u[a]
// One thread per row r = b*T + t. Two passes over A (25 each).
// W half staged in smem in native [d][a] layout -> coalesced load, float4 LDS
// broadcast in compute. x staged via padded smem tile to keep global loads
// coalesced (row-per-thread direct LDG would cost 32 L1 wavefronts/instr).
// ---------------------------------------------------------------------------
__global__ __launch_bounds__(128) void score_kernel(
    const float* __restrict__ x, const float* __restrict__ W,
    const float* __restrict__ bias, const float* __restrict__ u)
{
    __shared__ __align__(16) float sW[D_][28];     // 25 used + pad to 112B rows (16B aligned)
    __shared__ float xs[ROWS][DC + 1];             // pitch 17 -> conflict-free column reads
    __shared__ float sb[AH], su[AH];

    const int tid  = threadIdx.x;
    const int row0 = blockIdx.x * ROWS;
    const int row  = row0 + tid;

    float score = 0.0f;

    for (int h = 0; h < 2; ++h) {
        const int a0 = h * AH;

        // Stage W half: sW[d][a] = W[d*A + a0 + a]. Consecutive i -> consecutive a
        // -> ~2 lines per warp transaction. 6400 elements, 50 per thread.
        for (int i = tid; i < D_ * AH; i += 128) {
            int d = i / AH;
            int a = i - d * AH;
            sW[d][a] = W[d * A_ + a0 + a];
        }
        if (tid < AH) { sb[tid] = bias[a0 + tid]; su[tid] = u[a0 + tid]; }
        __syncthreads();

        float acc[AH];
        #pragma unroll
        for (int a = 0; a < AH; ++a) acc[a] = sb[a];

        for (int c0 = 0; c0 < D_; c0 += DC) {
            __syncthreads();  // xs reuse from previous tile
            // Stage x tile [128 rows x 16 cols] with float4 loads (coalesced in
            // groups of 4 lanes per row, 8 rows per warp instruction).
            #pragma unroll
            for (int k = 0; k < 4; ++k) {
                int e  = k * 128 + tid;      // 0..511 float4 slots
                int r  = e >> 2;             // 0..127
                int c4 = (e & 3) << 2;       // 0,4,8,12
                float4 v = *(const float4*)(x + (size_t)(row0 + r) * D_ + c0 + c4);
                xs[r][c4 + 0] = v.x; xs[r][c4 + 1] = v.y;
                xs[r][c4 + 2] = v.z; xs[r][c4 + 3] = v.w;
            }
            __syncthreads();

            float xv[DC];
            #pragma unroll
            for (int j = 0; j < DC; ++j) xv[j] = xs[tid][j];  // conflict-free (pitch 17)

            #pragma unroll
            for (int j = 0; j < DC; ++j) {
                const int d = c0 + j;
                const float xj = xv[j];
                #pragma unroll
                for (int g = 0; g < 6; ++g) {
                    float4 w4 = *(const float4*)&sW[d][g * 4];  // broadcast LDS.128
                    acc[g * 4 + 0] += xj * w4.x;
                    acc[g * 4 + 1] += xj * w4.y;
                    acc[g * 4 + 2] += xj * w4.z;
                    acc[g * 4 + 3] += xj * w4.w;
                }
                acc[24] += xj * sW[d][24];
            }
        }

        #pragma unroll
        for (int a = 0; a < AH; ++a) score += tanhf(acc[a]) * su[a];
        __syncthreads();  // before overwriting sW/sb/su for next half
    }

    g_scores[row] = score;
}

// ---------------------------------------------------------------------------
// Kernel 2: per batch b: w[t] = exp(score[b,t]); s = sum_t w[t];
//           out[b,d] = (1/(s+EPS)) * sum_t x[b,t,d] * w[t]
// Grid (B, 2): each block handles 128 of the 256 d-columns. Coalesced 512B
// reads per t. Pure HBM-bound pass over x (128 MB).
// ---------------------------------------------------------------------------
__global__ __launch_bounds__(128) void pool_kernel(
    const float* __restrict__ x, float* __restrict__ out)
{
    __shared__ float w[T_];
    __shared__ float red[128];

    const int b   = blockIdx.x;
    const int dh  = blockIdx.y;
    const int tid = threadIdx.x;

    float p = 0.0f;
    #pragma unroll
    for (int k = 0; k < 4; ++k) {
        float e = expf(g_scores[b * T_ + k * 128 + tid]);
        w[k * 128 + tid] = e;
        p += e;
    }
    red[tid] = p;
    __syncthreads();
    #pragma unroll
    for (int s = 64; s > 0; s >>= 1) {
        if (tid < s) red[tid] += red[tid + s];
        __syncthreads();
    }
    const float inv = 1.0f / (red[0] + 1e-7f);

    const int d = dh * 128 + tid;
    const float* xb = x + (size_t)b * T_ * D_ + d;

    float acc = 0.0f;
    #pragma unroll 8
    for (int t = 0; t < T_; ++t)
        acc += xb[(size_t)t * D_] * w[t];

    out[b * D_ + d] = acc * inv;
}

extern "C" void kernel_launch(void* const* d_in, const int* in_sizes, int n_in,
                              void* d_out, int out_size)
{
    const float* x  = (const float*)d_in[0];
    const float* W  = (const float*)d_in[1];
    const float* bb = (const float*)d_in[2];
    const float* u  = (const float*)d_in[3];
    float* out = (float*)d_out;

    score_kernel<<<(B_ * T_) / ROWS, 128>>>(x, W, bb, u);
    pool_kernel<<<dim3(B_, 2), 128>>>(x, out);
}

// round 2
// speedup vs baseline: 1.3776x; 1.3776x over previous
#include <cuda_runtime.h>
#include <math.h>

// Fixed shapes.
#define B_ 256
#define T_ 512
#define D_ 256
#define A_ 50
#define ROWS 128   // rows (b*t) per block == T/4, so each block is within one batch
#define DC 16      // d-chunk staged per tile

// Scratch: un-normalized pooled sums and per-batch exp-sums (zeroed by init_kernel).
__device__ float g_pool[B_ * D_];
__device__ float g_esum[B_];

__global__ __launch_bounds__(512) void init_kernel()
{
    int i = blockIdx.x * 512 + threadIdx.x;
    g_pool[i] = 0.0f;                 // grid*block == B_*D_ exactly
    if (i < B_) g_esum[i] = 0.0f;
}

// ---------------------------------------------------------------------------
// Fused kernel: for each 128-row slice (quarter of one batch):
//   1) acc[a] = x_row . W[:,a] + b[a]   (register-tiled GEMM, W in smem)
//   2) score  = sum_a tanh(acc[a]) * u[a];  e = exp(score)
//   3) partial pool: g_pool[b,:] += sum_t e_t * x[t,:]  (x re-read, L2-hot)
//      g_esum[b] += sum_t e_t
// ---------------------------------------------------------------------------
__global__ __launch_bounds__(128) void score_pool_kernel(
    const float* __restrict__ x, const float* __restrict__ W,
    const float* __restrict__ bias, const float* __restrict__ u)
{
    __shared__ __align__(16) float sW[D_][52];   // 50 used, pitch 52 (16B-aligned rows)
    __shared__ float xs[ROWS][DC + 1];           // pitch 17 -> conflict-free column reads
    __shared__ float sb[A_], su[A_];
    __shared__ float se[ROWS];
    __shared__ float wsum[4];

    const int tid  = threadIdx.x;
    const int row0 = blockIdx.x * ROWS;
    const int b    = row0 / T_;

    // Stage full W [256][50] coalesced (consecutive i -> consecutive gmem addr).
    for (int i = tid; i < D_ * A_; i += 128) {
        int d = i / A_;
        int a = i - d * A_;
        sW[d][a] = W[i];
    }
    if (tid < A_) { sb[tid] = bias[tid]; su[tid] = u[tid]; }
    __syncthreads();

    float acc[A_];
    #pragma unroll
    for (int a = 0; a < A_; ++a) acc[a] = sb[a];

    for (int c0 = 0; c0 < D_; c0 += DC) {
        // Stage x tile [128 rows x 16 cols] with coalesced float4 loads.
        #pragma unroll
        for (int k = 0; k < 4; ++k) {
            int e  = k * 128 + tid;
            int r  = e >> 2;
            int c4 = (e & 3) << 2;
            float4 v = *(const float4*)(x + (size_t)(row0 + r) * D_ + c0 + c4);
            xs[r][c4 + 0] = v.x; xs[r][c4 + 1] = v.y;
            xs[r][c4 + 2] = v.z; xs[r][c4 + 3] = v.w;
        }
        __syncthreads();

        #pragma unroll
        for (int j = 0; j < DC; ++j) {
            const float xj = xs[tid][j];          // pitch 17 -> no conflicts
            const float* wr = sW[c0 + j];
            #pragma unroll
            for (int g = 0; g < 12; ++g) {
                float4 w4 = *(const float4*)(wr + g * 4);   // broadcast LDS.128
                acc[g * 4 + 0] += xj * w4.x;
                acc[g * 4 + 1] += xj * w4.y;
                acc[g * 4 + 2] += xj * w4.z;
                acc[g * 4 + 3] += xj * w4.w;
            }
            acc[48] += xj * wr[48];
            acc[49] += xj * wr[49];
        }
        __syncthreads();   // before restaging xs
    }

    // Row score -> exp weight.
    float score = 0.0f;
    #pragma unroll
    for (int a = 0; a < A_; ++a) score += tanhf(acc[a]) * su[a];
    float e = expf(score);
    se[tid] = e;

    // Block-sum of e -> atomic into per-batch accumulator.
    float s = e;
    #pragma unroll
    for (int o = 16; o; o >>= 1) s += __shfl_xor_sync(0xFFFFFFFFu, s, o);
    if ((tid & 31) == 0) wsum[tid >> 5] = s;
    __syncthreads();     // also publishes se[] to all threads
    if (tid == 0) atomicAdd(&g_esum[b], wsum[0] + wsum[1] + wsum[2] + wsum[3]);

    // Weighted pool over this block's 128 rows. x tile is L2-hot (just streamed).
    // Thread layout: tc = which half of the 128 rows, g = float4 column group.
    const int tc = tid >> 6;          // 0..1
    const int g  = tid & 63;          // 0..63  -> d = 4g..4g+3 (coalesced per warp)
    const float* xb = x + (size_t)(row0 + tc * 64) * D_ + g * 4;

    float ax = 0.0f, ay = 0.0f, az = 0.0f, aw = 0.0f;
    #pragma unroll 8
    for (int tt = 0; tt < 64; ++tt) {
        float w  = se[tc * 64 + tt];
        float4 v = *(const float4*)(xb + (size_t)tt * D_);
        ax += v.x * w; ay += v.y * w; az += v.z * w; aw += v.w * w;
    }
    float* dst = &g_pool[b * D_ + g * 4];
    atomicAdd(dst + 0, ax);
    atomicAdd(dst + 1, ay);
    atomicAdd(dst + 2, az);
    atomicAdd(dst + 3, aw);
}

__global__ __launch_bounds__(512) void finalize_kernel(float* __restrict__ out)
{
    int i = blockIdx.x * 512 + threadIdx.x;     // 0 .. B_*D_-1
    int b = i >> 8;                             // D_ == 256
    out[i] = g_pool[i] / (g_esum[b] + 1e-7f);
}

extern "C" void kernel_launch(void* const* d_in, const int* in_sizes, int n_in,
                              void* d_out, int out_size)
{
    const float* x  = (const float*)d_in[0];
    const float* W  = (const float*)d_in[1];
    const float* bb = (const float*)d_in[2];
    const float* u  = (const float*)d_in[3];
    float* out = (float*)d_out;

    init_kernel<<<(B_ * D_) / 512, 512>>>();
    score_pool_kernel<<<(B_ * T_) / ROWS, 128>>>(x, W, bb, u);
    finalize_kernel<<<(B_ * D_) / 512, 512>>>(out);
}

// round 4
// speedup vs baseline: 1.4431x; 1.0476x over previous
#include <cuda_runtime.h>
#include <math.h>

// Fixed shapes.
#define B_ 256
#define T_ 512
#define D_ 256
#define A_ 50
#define AP 25      // packed f32x2 accumulator pairs (A_/2)
#define ROWS 128   // rows (b*t) per block == T/4, so each block is within one batch
#define DC 16      // d-chunk staged per tile

typedef unsigned long long u64;

// Scratch: un-normalized pooled sums and per-batch exp-sums (zeroed by init_kernel).
__device__ float g_pool[B_ * D_];
__device__ float g_esum[B_];

__global__ __launch_bounds__(512) void init_kernel()
{
    int i = blockIdx.x * 512 + threadIdx.x;
    g_pool[i] = 0.0f;                 // grid*block == B_*D_ exactly
    if (i < B_) g_esum[i] = 0.0f;
}

__device__ __forceinline__ float tanh_fast(float v)
{
    float r;
    asm("tanh.approx.f32 %0, %1;" : "=f"(r) : "f"(v));
    return r;
}

// ---------------------------------------------------------------------------
// Fused kernel, f32x2 packed math:
//   1) acc2[p] = packed pair over a=(2p, 2p+1) of x_row.W[:,a] + b[a]
//      via fma.rn.f32x2 (FFMA2) -> 2x fp32 FMA throughput on sm_103a.
//   2) score = sum_a tanh(acc[a]) * u[a];  e = exp(score)
//   3) partial pool: g_pool[b,:] += sum_t e_t * x[t,:]  (x re-read, L2-hot)
// ---------------------------------------------------------------------------
__global__ __launch_bounds__(128) void score_pool_kernel(
    const float* __restrict__ x, const float* __restrict__ W,
    const float* __restrict__ bias, const float* __restrict__ u)
{
    __shared__ __align__(16) float sW[D_][52];   // 50 used, pitch 52 -> rows 16B-aligned (208B)
    __shared__ float xs[ROWS][DC + 1];           // pitch 17 -> conflict-free column reads
    __shared__ float sb[A_], su[A_];
    __shared__ float se[ROWS];
    __shared__ float wsum[4];

    const int tid  = threadIdx.x;
    const int row0 = blockIdx.x * ROWS;
    const int b    = row0 / T_;

    // Stage full W [256][50] coalesced.
    for (int i = tid; i < D_ * A_; i += 128) {
        int d = i / A_;
        int a = i - d * A_;
        sW[d][a] = W[i];
    }
    if (tid < A_) { sb[tid] = bias[tid]; su[tid] = u[tid]; }
    __syncthreads();

    // Packed accumulators initialized with bias pairs: acc2[p] = {b[2p], b[2p+1]}.
    u64 acc2[AP];
    #pragma unroll
    for (int p = 0; p < AP; ++p)
        asm("mov.b64 %0, {%1, %2};" : "=l"(acc2[p]) : "f"(sb[2 * p]), "f"(sb[2 * p + 1]));

    for (int c0 = 0; c0 < D_; c0 += DC) {
        // Stage x tile [128 rows x 16 cols] with coalesced float4 loads.
        #pragma unroll
        for (int k = 0; k < 4; ++k) {
            int e  = k * 128 + tid;
            int r  = e >> 2;
            int c4 = (e & 3) << 2;
            float4 v = *(const float4*)(x + (size_t)(row0 + r) * D_ + c0 + c4);
            xs[r][c4 + 0] = v.x; xs[r][c4 + 1] = v.y;
            xs[r][c4 + 2] = v.z; xs[r][c4 + 3] = v.w;
        }
        __syncthreads();

        #pragma unroll
        for (int j = 0; j < DC; ++j) {
            const float xj = xs[tid][j];          // conflict-free LDS, pitch 17
            u64 xj2;
            asm("mov.b64 %0, {%1, %1};" : "=l"(xj2) : "f"(xj));
            const float* wr = sW[c0 + j];
            #pragma unroll
            for (int g = 0; g < 12; ++g) {
                // LDS.128 -> 4 consecutive floats wr[4g..4g+3] = 2 packed pairs.
                ulonglong2 w2 = *(const ulonglong2*)(wr + g * 4);
                asm("fma.rn.f32x2 %0, %1, %2, %0;" : "+l"(acc2[2 * g])     : "l"(xj2), "l"(w2.x));
                asm("fma.rn.f32x2 %0, %1, %2, %0;" : "+l"(acc2[2 * g + 1]) : "l"(xj2), "l"(w2.y));
            }
            u64 w48 = *(const u64*)(wr + 48);     // LDS.64 -> pair (a=48,49)
            asm("fma.rn.f32x2 %0, %1, %2, %0;" : "+l"(acc2[24]) : "l"(xj2), "l"(w48));
        }
        __syncthreads();   // before restaging xs
    }

    // Row score -> exp weight.
    float score = 0.0f;
    #pragma unroll
    for (int p = 0; p < AP; ++p) {
        float lo, hi;
        asm("mov.b64 {%0, %1}, %2;" : "=f"(lo), "=f"(hi) : "l"(acc2[p]));
        score += tanh_fast(lo) * su[2 * p] + tanh_fast(hi) * su[2 * p + 1];
    }
    float e = __expf(score);
    se[tid] = e;

    // Block-sum of e -> atomic into per-batch accumulator.
    float s = e;
    #pragma unroll
    for (int o = 16; o; o >>= 1) s += __shfl_xor_sync(0xFFFFFFFFu, s, o);
    if ((tid & 31) == 0) wsum[tid >> 5] = s;
    __syncthreads();     // also publishes se[] to all threads
    if (tid == 0) atomicAdd(&g_esum[b], wsum[0] + wsum[1] + wsum[2] + wsum[3]);

    // Weighted pool over this block's 128 rows (x tile L2-hot).
    const int tc = tid >> 6;          // 0..1 : which half of the 128 rows
    const int g  = tid & 63;          // 0..63 -> d = 4g..4g+3 (coalesced per warp)
    const float* xb = x + (size_t)(row0 + tc * 64) * D_ + g * 4;

    float ax = 0.0f, ay = 0.0f, az = 0.0f, aw = 0.0f;
    #pragma unroll 8
    for (int tt = 0; tt < 64; ++tt) {
        float w  = se[tc * 64 + tt];
        float4 v = *(const float4*)(xb + (size_t)tt * D_);
        ax += v.x * w; ay += v.y * w; az += v.z * w; aw += v.w * w;
    }
    float* dst = &g_pool[b * D_ + g * 4];
    atomicAdd(dst + 0, ax);
    atomicAdd(dst + 1, ay);
    atomicAdd(dst + 2, az);
    atomicAdd(dst + 3, aw);
}

__global__ __launch_bounds__(512) void finalize_kernel(float* __restrict__ out)
{
    int i = blockIdx.x * 512 + threadIdx.x;     // 0 .. B_*D_-1
    int b = i >> 8;                             // D_ == 256
    out[i] = g_pool[i] / (g_esum[b] + 1e-7f);
}

extern "C" void kernel_launch(void* const* d_in, const int* in_sizes, int n_in,
                              void* d_out, int out_size)
{
    const float* x  = (const float*)d_in[0];
    const float* W  = (const float*)d_in[1];
    const float* bb = (const float*)d_in[2];
    const float* u  = (const float*)d_in[3];
    float* out = (float*)d_out;

    init_kernel<<<(B_ * D_) / 512, 512>>>();
    score_pool_kernel<<<(B_ * T_) / ROWS, 128>>>(x, W, bb, u);
    finalize_kernel<<<(B_ * D_) / 512, 512>>>(out);
}

// round 6
// speedup vs baseline: 2.8672x; 1.9868x over previous
#include <cuda_runtime.h>
#include <cuda_bf16.h>
#include <math.h>
#include <stdint.h>

#define B_ 256
#define T_ 512
#define D_ 256
#define A_ 50
#define NP 56          // padded N (multiple of 8)
#define ROWS 128       // M tile per CTA (quarter of one batch)
#define KC 32          // K chunk per staging round
#define PA 40          // smem pitch in bf16 (80B) -> conflict-free ldmatrix

typedef unsigned long long u64;

__device__ float g_pool[B_ * D_];
__device__ float g_esum[B_];
__device__ __nv_bfloat16 g_wt_hi[NP * D_];   // W^T padded [n][k], bf16 hi
__device__ __nv_bfloat16 g_wt_lo[NP * D_];   // residual lo

__device__ __forceinline__ uint32_t smem_u32(const void* p) {
    uint32_t a;
    asm("{ .reg .u64 t; cvta.to.shared.u64 t, %1; cvt.u32.u64 %0, t; }" : "=r"(a) : "l"(p));
    return a;
}
__device__ __forceinline__ void ldx4(uint32_t* r, uint32_t addr) {
    asm volatile("ldmatrix.sync.aligned.m8n8.x4.shared.b16 {%0,%1,%2,%3}, [%4];"
                 : "=r"(r[0]), "=r"(r[1]), "=r"(r[2]), "=r"(r[3]) : "r"(addr));
}
__device__ __forceinline__ void ldx2(uint32_t* r, uint32_t addr) {
    asm volatile("ldmatrix.sync.aligned.m8n8.x2.shared.b16 {%0,%1}, [%2];"
                 : "=r"(r[0]), "=r"(r[1]) : "r"(addr));
}
__device__ __forceinline__ void mma16816(float* d, const uint32_t* a, const uint32_t* b) {
    asm volatile(
        "mma.sync.aligned.m16n8k16.row.col.f32.bf16.bf16.f32 "
        "{%0,%1,%2,%3}, {%4,%5,%6,%7}, {%8,%9}, {%0,%1,%2,%3};"
        : "+f"(d[0]), "+f"(d[1]), "+f"(d[2]), "+f"(d[3])
        : "r"(a[0]), "r"(a[1]), "r"(a[2]), "r"(a[3]), "r"(b[0]), "r"(b[1]));
}

struct __align__(16) Smem {
    __nv_bfloat16 a_hi[ROWS * PA];   // 10240 B
    __nv_bfloat16 a_lo[ROWS * PA];   // 10240 B
    __nv_bfloat16 b_hi[NP * PA];     //  4480 B
    __nv_bfloat16 b_lo[NP * PA];     //  4480 B
    float sb[NP], su[NP];
    float se[ROWS];
    float wsum[4];
};

// Prep: zero accumulators + transposed/padded bf16 hi/lo copies of W.
__global__ __launch_bounds__(512) void prep_kernel(const float* __restrict__ W)
{
    int i = blockIdx.x * 512 + threadIdx.x;    // covers B_*D_ = 65536
    g_pool[i] = 0.0f;
    if (i < B_) g_esum[i] = 0.0f;
    if (i < NP * D_) {
        int n = i / D_, k = i - n * D_;
        float w = (n < A_) ? W[k * A_ + n] : 0.0f;
        __nv_bfloat16 hi = __float2bfloat16(w);
        __nv_bfloat16 lo = __float2bfloat16(w - __bfloat162float(hi));
        g_wt_hi[i] = hi;
        g_wt_lo[i] = lo;
    }
}

__global__ __launch_bounds__(128) void score_pool_mma(
    const float* __restrict__ x, const float* __restrict__ bias,
    const float* __restrict__ u)
{
    __shared__ Smem sm;

    const int tid  = threadIdx.x;
    const int wid  = tid >> 5;
    const int lane = tid & 31;
    const int row0 = blockIdx.x * ROWS;
    const int b    = blockIdx.x >> 2;          // 4 CTAs per batch

    if (tid < NP) {
        sm.sb[tid] = (tid < A_) ? bias[tid] : 0.0f;
        sm.su[tid] = (tid < A_) ? u[tid]    : 0.0f;
    }

    float acc[2][7][4];
    #pragma unroll
    for (int mt = 0; mt < 2; ++mt)
        #pragma unroll
        for (int nt = 0; nt < 7; ++nt)
            #pragma unroll
            for (int q = 0; q < 4; ++q) acc[mt][nt][q] = 0.0f;

    const uint32_t ahB = smem_u32(sm.a_hi), alB = smem_u32(sm.a_lo);
    const uint32_t bhB = smem_u32(sm.b_hi), blB = smem_u32(sm.b_lo);

    // ldmatrix per-lane address components (PTX ISA fragment layouts):
    const int sub      = lane >> 3;
    const int arow_off = (sub & 1) * 8 + (lane & 7);   // A: x4 tile row
    const int ak_off   = (sub >> 1) * 8;               // A: x4 tile k-half
    const int bn_off   = lane & 7;                     // B: x2 tile row (n)
    const int bk_off   = ((lane >> 3) & 1) * 8;        // B: x2 tile k-half

    for (int kc = 0; kc < D_ / KC; ++kc) {
        if (kc) __syncthreads();   // previous ldmatrix done before restage

        // ---- stage A chunk: x[128][KC] fp32 -> bf16 hi/lo (pitch PA)
        #pragma unroll
        for (int it = 0; it < 8; ++it) {
            int i  = it * 128 + tid;        // 1024 float4 slots
            int r  = i >> 3;                // 8 float4 per row
            int c4 = (i & 7) << 2;
            float4 v = *(const float4*)(x + (size_t)(row0 + r) * D_ + kc * KC + c4);
            __nv_bfloat16 h0 = __float2bfloat16(v.x), h1 = __float2bfloat16(v.y);
            __nv_bfloat16 h2 = __float2bfloat16(v.z), h3 = __float2bfloat16(v.w);
            __nv_bfloat16 l0 = __float2bfloat16(v.x - __bfloat162float(h0));
            __nv_bfloat16 l1 = __float2bfloat16(v.y - __bfloat162float(h1));
            __nv_bfloat16 l2 = __float2bfloat16(v.z - __bfloat162float(h2));
            __nv_bfloat16 l3 = __float2bfloat16(v.w - __bfloat162float(h3));
            uint2 ph, pl;
            ph.x = ((uint32_t)__bfloat16_as_ushort(h1) << 16) | __bfloat16_as_ushort(h0);
            ph.y = ((uint32_t)__bfloat16_as_ushort(h3) << 16) | __bfloat16_as_ushort(h2);
            pl.x = ((uint32_t)__bfloat16_as_ushort(l1) << 16) | __bfloat16_as_ushort(l0);
            pl.y = ((uint32_t)__bfloat16_as_ushort(l3) << 16) | __bfloat16_as_ushort(l2);
            int off = r * PA + c4;
            *(uint2*)&sm.a_hi[off] = ph;
            *(uint2*)&sm.a_lo[off] = pl;
        }
        // ---- stage B chunk: Wt[56][KC] hi/lo
        for (int i = tid; i < NP * 8; i += 128) {
            int n = i >> 3;
            int q = (i & 7) << 2;
            uint2 vh = *(const uint2*)&g_wt_hi[n * D_ + kc * KC + q];
            uint2 vl = *(const uint2*)&g_wt_lo[n * D_ + kc * KC + q];
            *(uint2*)&sm.b_hi[n * PA + q] = vh;
            *(uint2*)&sm.b_lo[n * PA + q] = vl;
        }
        __syncthreads();

        #pragma unroll
        for (int ks = 0; ks < 2; ++ks) {
            const int k0 = ks * 16;
            uint32_t bh[7][2], bl[7][2];
            #pragma unroll
            for (int nt = 0; nt < 7; ++nt) {
                uint32_t off = (uint32_t)(((nt * 8 + bn_off) * PA + k0 + bk_off) * 2);
                ldx2(bh[nt], bhB + off);
                ldx2(bl[nt], blB + off);
            }
            #pragma unroll
            for (int mt = 0; mt < 2; ++mt) {
                uint32_t off = (uint32_t)(((wid * 32 + mt * 16 + arow_off) * PA
                                           + k0 + ak_off) * 2);
                uint32_t ah[4], al[4];
                ldx4(ah, ahB + off);
                ldx4(al, alB + off);
                #pragma unroll
                for (int nt = 0; nt < 7; ++nt) {
                    mma16816(acc[mt][nt], ah, bh[nt]);   // hi*hi
                    mma16816(acc[mt][nt], ah, bl[nt]);   // hi*lo
                    mma16816(acc[mt][nt], al, bh[nt]);   // lo*hi
                }
            }
        }
    }

    // ---- epilogue: score rows. D frag: row=lane/4 (+8), col=2*(lane&3)+8*nt (+1).
    #pragma unroll
    for (int mt = 0; mt < 2; ++mt) {
        float plo = 0.0f, phi = 0.0f;
        #pragma unroll
        for (int nt = 0; nt < 7; ++nt) {
            int c = nt * 8 + 2 * (lane & 3);
            plo += tanhf(acc[mt][nt][0] + sm.sb[c])     * sm.su[c];
            plo += tanhf(acc[mt][nt][1] + sm.sb[c + 1]) * sm.su[c + 1];
            phi += tanhf(acc[mt][nt][2] + sm.sb[c])     * sm.su[c];
            phi += tanhf(acc[mt][nt][3] + sm.sb[c + 1]) * sm.su[c + 1];
        }
        plo += __shfl_xor_sync(0xFFFFFFFFu, plo, 1);
        plo += __shfl_xor_sync(0xFFFFFFFFu, plo, 2);
        phi += __shfl_xor_sync(0xFFFFFFFFu, phi, 1);
        phi += __shfl_xor_sync(0xFFFFFFFFu, phi, 2);
        if ((lane & 3) == 0) {
            int r = wid * 32 + mt * 16 + (lane >> 2);
            sm.se[r]     = expf(plo);
            sm.se[r + 8] = expf(phi);
        }
    }
    __syncthreads();

    // Block sum of e -> per-batch accumulator.
    float e = sm.se[tid];
    float s = e;
    #pragma unroll
    for (int o = 16; o; o >>= 1) s += __shfl_xor_sync(0xFFFFFFFFu, s, o);
    if ((lane == 0)) sm.wsum[wid] = s;
    __syncthreads();
    if (tid == 0) atomicAdd(&g_esum[b], sm.wsum[0] + sm.wsum[1] + sm.wsum[2] + sm.wsum[3]);

    // ---- fused pool over this CTA's 128 rows (x L2-hot: just streamed).
    const int tc = tid >> 6;
    const int g  = tid & 63;
    const float* xb = x + (size_t)(row0 + tc * 64) * D_ + g * 4;

    float ax = 0.0f, ay = 0.0f, az = 0.0f, aw = 0.0f;
    #pragma unroll 8
    for (int tt = 0; tt < 64; ++tt) {
        float w  = sm.se[tc * 64 + tt];
        float4 v = *(const float4*)(xb + (size_t)tt * D_);
        ax += v.x * w; ay += v.y * w; az += v.z * w; aw += v.w * w;
    }
    float* dst = &g_pool[b * D_ + g * 4];
    atomicAdd(dst + 0, ax);
    atomicAdd(dst + 1, ay);
    atomicAdd(dst + 2, az);
    atomicAdd(dst + 3, aw);
}

__global__ __launch_bounds__(512) void finalize_kernel(float* __restrict__ out)
{
    int i = blockIdx.x * 512 + threadIdx.x;
    int b = i >> 8;
    out[i] = g_pool[i] / (g_esum[b] + 1e-7f);
}

extern "C" void kernel_launch(void* const* d_in, const int* in_sizes, int n_in,
                              void* d_out, int out_size)
{
    const float* x  = (const float*)d_in[0];
    const float* W  = (const float*)d_in[1];
    const float* bb = (const float*)d_in[2];
    const float* u  = (const float*)d_in[3];
    float* out = (float*)d_out;

    prep_kernel<<<(B_ * D_) / 512, 512>>>(W);
    score_pool_mma<<<(B_ * T_) / ROWS, 128>>>(x, bb, u);
    finalize_kernel<<<(B_ * D_) / 512, 512>>>(out);
}

// round 8
// speedup vs baseline: 3.0451x; 1.0620x over previous
#include <cuda_runtime.h>
#include <cuda_bf16.h>
#include <math.h>
#include <stdint.h>

#define B_ 256
#define T_ 512
#define D_ 256
#define A_ 50
#define NP 56          // padded N (multiple of 8)
#define ROWS 128       // M tile per CTA (quarter of one batch)
#define KC 32          // K chunk per staging round
#define PA 40          // smem pitch in bf16 (80B rows: 16B-aligned ldmatrix rows)
#define NCHUNK (D_ / KC)

typedef unsigned long long u64;

__device__ __align__(16) float g_pool_part[(B_ * T_ / ROWS) * D_];  // per-CTA pool partials
__device__ float g_esum_part[B_ * T_ / ROWS];                        // per-CTA exp-sum partials

__device__ __forceinline__ uint32_t smem_u32(const void* p) {
    uint32_t a;
    asm("{ .reg .u64 t; cvta.to.shared.u64 t, %1; cvt.u32.u64 %0, t; }" : "=r"(a) : "l"(p));
    return a;
}
__device__ __forceinline__ void ldx4(uint32_t* r, uint32_t addr) {
    asm volatile("ldmatrix.sync.aligned.m8n8.x4.shared.b16 {%0,%1,%2,%3}, [%4];"
                 : "=r"(r[0]), "=r"(r[1]), "=r"(r[2]), "=r"(r[3]) : "r"(addr));
}
__device__ __forceinline__ void ldx2(uint32_t* r, uint32_t addr) {
    asm volatile("ldmatrix.sync.aligned.m8n8.x2.shared.b16 {%0,%1}, [%2];"
                 : "=r"(r[0]), "=r"(r[1]) : "r"(addr));
}
__device__ __forceinline__ void mma16816(float* d, const uint32_t* a, const uint32_t* b) {
    asm volatile(
        "mma.sync.aligned.m16n8k16.row.col.f32.bf16.bf16.f32 "
        "{%0,%1,%2,%3}, {%4,%5,%6,%7}, {%8,%9}, {%0,%1,%2,%3};"
        : "+f"(d[0]), "+f"(d[1]), "+f"(d[2]), "+f"(d[3])
        : "r"(a[0]), "r"(a[1]), "r"(a[2]), "r"(a[3]), "r"(b[0]), "r"(b[1]));
}
// Packed split: {hi1,hi0} = bf16x2(y,x); residuals lo = v - float(hi), packed too.
__device__ __forceinline__ void split2(float vx, float vy, uint32_t& ph, uint32_t& pl) {
    asm("cvt.rn.bf16x2.f32 %0, %1, %2;" : "=r"(ph) : "f"(vy), "f"(vx));
    float h0 = __uint_as_float(ph << 16);
    float h1 = __uint_as_float(ph & 0xFFFF0000u);
    float l0 = vx - h0, l1 = vy - h1;
    asm("cvt.rn.bf16x2.f32 %0, %1, %2;" : "=r"(pl) : "f"(l1), "f"(l0));
}

struct __align__(16) Smem {
    __nv_bfloat16 a_hi[ROWS * PA];   // 10240 B
    __nv_bfloat16 a_lo[ROWS * PA];   // 10240 B
    __nv_bfloat16 b_hi[NP * PA];     //  4480 B
    __nv_bfloat16 b_lo[NP * PA];     //  4480 B
    float sb[NP], su[NP];
    float se[ROWS];
    float wsum[4];
    float pp[64][4];
};

__global__ __launch_bounds__(128, 3) void score_pool_mma(
    const float* __restrict__ x, const float* __restrict__ W,
    const float* __restrict__ bias, const float* __restrict__ u)
{
    __shared__ Smem sm;

    const int tid  = threadIdx.x;
    const int wid  = tid >> 5;
    const int lane = tid & 31;
    const int row0 = blockIdx.x * ROWS;

    if (tid < NP) {
        sm.sb[tid] = (tid < A_) ? bias[tid] : 0.0f;
        sm.su[tid] = (tid < A_) ? u[tid]    : 0.0f;
    }

    float acc[2][7][4];
    #pragma unroll
    for (int mt = 0; mt < 2; ++mt)
        #pragma unroll
        for (int nt = 0; nt < 7; ++nt)
            #pragma unroll
            for (int q = 0; q < 4; ++q) acc[mt][nt][q] = 0.0f;

    const uint32_t ahB = smem_u32(sm.a_hi), alB = smem_u32(sm.a_lo);
    const uint32_t bhB = smem_u32(sm.b_hi), blB = smem_u32(sm.b_lo);

    // ldmatrix per-lane address components:
    const int sub      = lane >> 3;
    const int arow_off = (sub & 1) * 8 + (lane & 7);
    const int ak_off   = (sub >> 1) * 8;
    const int bn_off   = lane & 7;
    const int bk_off   = ((lane >> 3) & 1) * 8;

    // A-staging geometry for this thread (8 float4 slots per chunk).
    const int ar  = tid >> 3;                // base row (tid/8), +16 per it
    const int ac4 = (tid & 7) << 2;          // col within chunk

    float4 apref[8];

    // ---- prologue: stage chunk 0 ----
    #pragma unroll
    for (int it = 0; it < 8; ++it)
        apref[it] = *(const float4*)(x + (size_t)(row0 + it * 16 + ar) * D_ + ac4);
    #pragma unroll
    for (int it = 0; it < 8; ++it) {
        uint2 ph, pl;
        split2(apref[it].x, apref[it].y, ph.x, pl.x);
        split2(apref[it].z, apref[it].w, ph.y, pl.y);
        int off = (it * 16 + ar) * PA + ac4;
        *(uint2*)&sm.a_hi[off] = ph;
        *(uint2*)&sm.a_lo[off] = pl;
    }
    #pragma unroll
    for (int j = 0; j < 14; ++j) {
        int i = j * 128 + tid;
        int n = i % NP, k = i / NP;
        float w = (n < A_) ? W[k * A_ + n] : 0.0f;
        uint32_t ph, pl;
        split2(w, 0.0f, ph, pl);
        sm.b_hi[n * PA + k] = __ushort_as_bfloat16((unsigned short)(ph & 0xFFFF));
        sm.b_lo[n * PA + k] = __ushort_as_bfloat16((unsigned short)(pl & 0xFFFF));
    }
    __syncthreads();

    for (int kc = 0; kc < NCHUNK; ++kc) {
        // ---- prefetch next A chunk (LDG latency overlaps the MMA below)
        if (kc + 1 < NCHUNK) {
            #pragma unroll
            for (int it = 0; it < 8; ++it)
                apref[it] = *(const float4*)(x + (size_t)(row0 + it * 16 + ar) * D_
                                             + (kc + 1) * KC + ac4);
        }

        // ---- MMA on staged chunk
        #pragma unroll
        for (int ks = 0; ks < 2; ++ks) {
            const int k0 = ks * 16;
            uint32_t bh[7][2], bl[7][2];
            #pragma unroll
            for (int nt = 0; nt < 7; ++nt) {
                uint32_t off = (uint32_t)(((nt * 8 + bn_off) * PA + k0 + bk_off) * 2);
                ldx2(bh[nt], bhB + off);
                ldx2(bl[nt], blB + off);
            }
            #pragma unroll
            for (int mt = 0; mt < 2; ++mt) {
                uint32_t off = (uint32_t)(((wid * 32 + mt * 16 + arow_off) * PA
                                           + k0 + ak_off) * 2);
                uint32_t ah[4], al[4];
                ldx4(ah, ahB + off);
                ldx4(al, alB + off);
                #pragma unroll
                for (int nt = 0; nt < 7; ++nt) {
                    mma16816(acc[mt][nt], ah, bh[nt]);   // hi*hi
                    mma16816(acc[mt][nt], ah, bl[nt]);   // hi*lo
                    mma16816(acc[mt][nt], al, bh[nt]);   // lo*hi
                }
            }
        }
        __syncthreads();   // all warps done reading smem

        // ---- store prefetched A + restage B for next chunk
        if (kc + 1 < NCHUNK) {
            #pragma unroll
            for (int it = 0; it < 8; ++it) {
                uint2 ph, pl;
                split2(apref[it].x, apref[it].y, ph.x, pl.x);
                split2(apref[it].z, apref[it].w, ph.y, pl.y);
                int off = (it * 16 + ar) * PA + ac4;
                *(uint2*)&sm.a_hi[off] = ph;
                *(uint2*)&sm.a_lo[off] = pl;
            }
            #pragma unroll
            for (int j = 0; j < 14; ++j) {
                int i = j * 128 + tid;
                int n = i % NP, k = i / NP;
                float w = (n < A_) ? W[((kc + 1) * KC + k) * A_ + n] : 0.0f;
                uint32_t ph, pl;
                split2(w, 0.0f, ph, pl);
                sm.b_hi[n * PA + k] = __ushort_as_bfloat16((unsigned short)(ph & 0xFFFF));
                sm.b_lo[n * PA + k] = __ushort_as_bfloat16((unsigned short)(pl & 0xFFFF));
            }
            __syncthreads();
        }
    }

    // ---- epilogue: scores. D frag: row=lane/4 (+8), col=2*(lane&3)+8*nt (+1).
    #pragma unroll
    for (int mt = 0; mt < 2; ++mt) {
        float plo = 0.0f, phi = 0.0f;
        #pragma unroll
        for (int nt = 0; nt < 7; ++nt) {
            int c = nt * 8 + 2 * (lane & 3);
            plo += tanhf(acc[mt][nt][0] + sm.sb[c])     * sm.su[c];
            plo += tanhf(acc[mt][nt][1] + sm.sb[c + 1]) * sm.su[c + 1];
            phi += tanhf(acc[mt][nt][2] + sm.sb[c])     * sm.su[c];
            phi += tanhf(acc[mt][nt][3] + sm.sb[c + 1]) * sm.su[c + 1];
        }
        plo += __shfl_xor_sync(0xFFFFFFFFu, plo, 1);
        plo += __shfl_xor_sync(0xFFFFFFFFu, plo, 2);
        phi += __shfl_xor_sync(0xFFFFFFFFu, phi, 1);
        phi += __shfl_xor_sync(0xFFFFFFFFu, phi, 2);
        if ((lane & 3) == 0) {
            int r = wid * 32 + mt * 16 + (lane >> 2);
            sm.se[r]     = expf(plo);
            sm.se[r + 8] = expf(phi);
        }
    }
    __syncthreads();

    // Block sum of e -> per-CTA partial (no atomics).
    float e = sm.se[tid];
    float s = e;
    #pragma unroll
    for (int o = 16; o; o >>= 1) s += __shfl_xor_sync(0xFFFFFFFFu, s, o);
    if (lane == 0) sm.wsum[wid] = s;
    __syncthreads();
    if (tid == 0)
        g_esum_part[blockIdx.x] = sm.wsum[0] + sm.wsum[1] + sm.wsum[2] + sm.wsum[3];

    // ---- fused pool over this CTA's 128 rows (x L2-hot: just streamed).
    const int tc = tid >> 6;
    const int g  = tid & 63;
    const float* xb = x + (size_t)(row0 + tc * 64) * D_ + g * 4;

    float ax = 0.0f, ay = 0.0f, az = 0.0f, aw = 0.0f;
    #pragma unroll 8
    for (int tt = 0; tt < 64; ++tt) {
        float w  = sm.se[tc * 64 + tt];
        float4 v = *(const float4*)(xb + (size_t)tt * D_);
        ax += v.x * w; ay += v.y * w; az += v.z * w; aw += v.w * w;
    }
    if (tc == 1) {
        sm.pp[g][0] = ax; sm.pp[g][1] = ay; sm.pp[g][2] = az; sm.pp[g][3] = aw;
    }
    __syncthreads();
    if (tc == 0) {
        float4 r;
        r.x = ax + sm.pp[g][0];
        r.y = ay + sm.pp[g][1];
        r.z = az + sm.pp[g][2];
        r.w = aw + sm.pp[g][3];
        *(float4*)&g_pool_part[blockIdx.x * D_ + g * 4] = r;
    }
}

__global__ __launch_bounds__(512) void finalize_kernel(float* __restrict__ out)
{
    int i = blockIdx.x * 512 + threadIdx.x;   // 0 .. B_*D_-1
    int b = i >> 8;                           // D_ == 256
    int d = i & 255;
    const float* pp = &g_pool_part[(4 * b) * D_ + d];
    float p = pp[0] + pp[D_] + pp[2 * D_] + pp[3 * D_];
    const float* ep = &g_esum_part[4 * b];
    float e = ep[0] + ep[1] + ep[2] + ep[3];
    out[i] = p / (e + 1e-7f);
}

extern "C" void kernel_launch(void* const* d_in, const int* in_sizes, int n_in,
                              void* d_out, int out_size)
{
    const float* x  = (const float*)d_in[0];
    const float* W  = (const float*)d_in[1];
    const float* bb = (const float*)d_in[2];
    const float* u  = (const float*)d_in[3];
    float* out = (float*)d_out;

    score_pool_mma<<<(B_ * T_) / ROWS, 128>>>(x, W, bb, u);
    finalize_kernel<<<(B_ * D_) / 512, 512>>>(out);
}

// round 9
// speedup vs baseline: 3.2959x; 1.0824x over previous
#include <cuda_runtime.h>
#include <cuda_bf16.h>
#include <math.h>
#include <stdint.h>

#define B_ 256
#define T_ 512
#define D_ 256
#define A_ 50
#define NP 56          // padded N (multiple of 8)
#define ROWS 128       // M tile per CTA (quarter of one batch)
#define KC 64          // K chunk per staging round
#define PA 72          // smem pitch in bf16 (144B rows: 16B-aligned, LDSM conflict-free)
#define NCHUNK (D_ / KC)

typedef unsigned long long u64;

__device__ __align__(16) float g_pool_part[(B_ * T_ / ROWS) * D_];  // per-CTA pool partials
__device__ float g_esum_part[B_ * T_ / ROWS];                        // per-CTA exp-sum partials

__device__ __forceinline__ uint32_t smem_u32(const void* p) {
    uint32_t a;
    asm("{ .reg .u64 t; cvta.to.shared.u64 t, %1; cvt.u32.u64 %0, t; }" : "=r"(a) : "l"(p));
    return a;
}
__device__ __forceinline__ void ldx4(uint32_t* r, uint32_t addr) {
    asm volatile("ldmatrix.sync.aligned.m8n8.x4.shared.b16 {%0,%1,%2,%3}, [%4];"
                 : "=r"(r[0]), "=r"(r[1]), "=r"(r[2]), "=r"(r[3]) : "r"(addr));
}
__device__ __forceinline__ void ldx2(uint32_t* r, uint32_t addr) {
    asm volatile("ldmatrix.sync.aligned.m8n8.x2.shared.b16 {%0,%1}, [%2];"
                 : "=r"(r[0]), "=r"(r[1]) : "r"(addr));
}
__device__ __forceinline__ void mma16816(float* d, const uint32_t* a, const uint32_t* b) {
    asm volatile(
        "mma.sync.aligned.m16n8k16.row.col.f32.bf16.bf16.f32 "
        "{%0,%1,%2,%3}, {%4,%5,%6,%7}, {%8,%9}, {%0,%1,%2,%3};"
        : "+f"(d[0]), "+f"(d[1]), "+f"(d[2]), "+f"(d[3])
        : "r"(a[0]), "r"(a[1]), "r"(a[2]), "r"(a[3]), "r"(b[0]), "r"(b[1]));
}
// Packed round: {bf16(y),bf16(x)} in one reg.
__device__ __forceinline__ uint32_t pack_bf2(float vx, float vy) {
    uint32_t p;
    asm("cvt.rn.bf16x2.f32 %0, %1, %2;" : "=r"(p) : "f"(vy), "f"(vx));
    return p;
}
// hi/lo split of one float.
__device__ __forceinline__ void split1(float v, __nv_bfloat16& h, __nv_bfloat16& l) {
    h = __float2bfloat16(v);
    l = __float2bfloat16(v - __bfloat162float(h));
}

struct __align__(16) Smem {
    __nv_bfloat16 a[ROWS * PA];      // 18432 B  (x rounded to bf16)
    __nv_bfloat16 b_hi[NP * PA];     //  8064 B  (W^T hi)
    __nv_bfloat16 b_lo[NP * PA];     //  8064 B  (W^T lo residual)
    float sb[NP], su[NP];
    float se[ROWS];
    float wsum[4];
    float pp[64][4];
};

__global__ __launch_bounds__(128, 4) void score_pool_mma(
    const float* __restrict__ x, const float* __restrict__ W,
    const float* __restrict__ bias, const float* __restrict__ u)
{
    __shared__ Smem sm;

    const int tid  = threadIdx.x;
    const int wid  = tid >> 5;
    const int lane = tid & 31;
    const int row0 = blockIdx.x * ROWS;

    if (tid < NP) {
        sm.sb[tid] = (tid < A_) ? bias[tid] : 0.0f;
        sm.su[tid] = (tid < A_) ? u[tid]    : 0.0f;
    }

    float acc[2][7][4];
    #pragma unroll
    for (int mt = 0; mt < 2; ++mt)
        #pragma unroll
        for (int nt = 0; nt < 7; ++nt)
            #pragma unroll
            for (int q = 0; q < 4; ++q) acc[mt][nt][q] = 0.0f;

    const uint32_t aB  = smem_u32(sm.a);
    const uint32_t bhB = smem_u32(sm.b_hi), blB = smem_u32(sm.b_lo);

    // ldmatrix per-lane address components:
    const int sub      = lane >> 3;
    const int arow_off = (sub & 1) * 8 + (lane & 7);
    const int ak_off   = (sub >> 1) * 8;
    const int bn_off   = lane & 7;
    const int bk_off   = ((lane >> 3) & 1) * 8;

    for (int kc = 0; kc < NCHUNK; ++kc) {
        if (kc) __syncthreads();   // previous MMA reads done before restage

        // ---- stage A chunk: x[128][64] fp32 -> bf16 (16 float4/thread, coalesced)
        #pragma unroll
        for (int it = 0; it < 16; ++it) {
            int s  = it * 128 + tid;       // 2048 float4 slots
            int r  = s >> 4;               // 16 float4 per row
            int c4 = (s & 15) << 2;
            float4 v = *(const float4*)(x + (size_t)(row0 + r) * D_ + kc * KC + c4);
            uint2 p;
            p.x = pack_bf2(v.x, v.y);
            p.y = pack_bf2(v.z, v.w);
            *(uint2*)&sm.a[r * PA + c4] = p;
        }
        // ---- stage B chunk: W[kc*64+k][n] -> hi/lo bf16 at b[n][k] (coalesced LDG over n)
        #pragma unroll
        for (int j = 0; j < 28; ++j) {
            int i = j * 128 + tid;         // 3584 = 64k x 56n slots
            int k = i / NP;
            int n = i - k * NP;
            float w = (n < A_) ? W[(kc * KC + k) * A_ + n] : 0.0f;
            __nv_bfloat16 h, l;
            split1(w, h, l);
            sm.b_hi[n * PA + k] = h;
            sm.b_lo[n * PA + k] = l;
        }
        __syncthreads();

        // ---- MMA on staged chunk: 4 k16 steps, 2 chains (x@Wh + x@Wl)
        #pragma unroll
        for (int ks = 0; ks < 4; ++ks) {
            const int k0 = ks * 16;
            uint32_t bh[7][2], bl[7][2];
            #pragma unroll
            for (int nt = 0; nt < 7; ++nt) {
                uint32_t off = (uint32_t)(((nt * 8 + bn_off) * PA + k0 + bk_off) * 2);
                ldx2(bh[nt], bhB + off);
                ldx2(bl[nt], blB + off);
            }
            #pragma unroll
            for (int mt = 0; mt < 2; ++mt) {
                uint32_t off = (uint32_t)(((wid * 32 + mt * 16 + arow_off) * PA
                                           + k0 + ak_off) * 2);
                uint32_t av[4];
                ldx4(av, aB + off);
                #pragma unroll
                for (int nt = 0; nt < 7; ++nt) {
                    mma16816(acc[mt][nt], av, bh[nt]);   // x @ W_hi
                    mma16816(acc[mt][nt], av, bl[nt]);   // x @ W_lo
                }
            }
        }
    }

    // ---- epilogue: scores. D frag: row=lane/4 (+8), col=2*(lane&3)+8*nt (+1).
    #pragma unroll
    for (int mt = 0; mt < 2; ++mt) {
        float plo = 0.0f, phi = 0.0f;
        #pragma unroll
        for (int nt = 0; nt < 7; ++nt) {
            int c = nt * 8 + 2 * (lane & 3);
            plo += tanhf(acc[mt][nt][0] + sm.sb[c])     * sm.su[c];
            plo += tanhf(acc[mt][nt][1] + sm.sb[c + 1]) * sm.su[c + 1];
            phi += tanhf(acc[mt][nt][2] + sm.sb[c])     * sm.su[c];
            phi += tanhf(acc[mt][nt][3] + sm.sb[c + 1]) * sm.su[c + 1];
        }
        plo += __shfl_xor_sync(0xFFFFFFFFu, plo, 1);
        plo += __shfl_xor_sync(0xFFFFFFFFu, plo, 2);
        phi += __shfl_xor_sync(0xFFFFFFFFu, phi, 1);
        phi += __shfl_xor_sync(0xFFFFFFFFu, phi, 2);
        if ((lane & 3) == 0) {
            int r = wid * 32 + mt * 16 + (lane >> 2);
            sm.se[r]     = expf(plo);
            sm.se[r + 8] = expf(phi);
        }
    }
    __syncthreads();

    // Block sum of e -> per-CTA partial (no atomics).
    float e = sm.se[tid];
    float s = e;
    #pragma unroll
    for (int o = 16; o; o >>= 1) s += __shfl_xor_sync(0xFFFFFFFFu, s, o);
    if (lane == 0) sm.wsum[wid] = s;
    __syncthreads();
    if (tid == 0)
        g_esum_part[blockIdx.x] = sm.wsum[0] + sm.wsum[1] + sm.wsum[2] + sm.wsum[3];

    // ---- fused pool over this CTA's 128 rows (x L2-hot: just streamed).
    const int tc = tid >> 6;
    const int g  = tid & 63;
    const float* xb = x + (size_t)(row0 + tc * 64) * D_ + g * 4;

    float ax = 0.0f, ay = 0.0f, az = 0.0f, aw = 0.0f;
    #pragma unroll 8
    for (int tt = 0; tt < 64; ++tt) {
        float w  = sm.se[tc * 64 + tt];
        float4 v = *(const float4*)(xb + (size_t)tt * D_);
        ax += v.x * w; ay += v.y * w; az += v.z * w; aw += v.w * w;
    }
    if (tc == 1) {
        sm.pp[g][0] = ax; sm.pp[g][1] = ay; sm.pp[g][2] = az; sm.pp[g][3] = aw;
    }
    __syncthreads();
    if (tc == 0) {
        float4 r;
        r.x = ax + sm.pp[g][0];
        r.y = ay + sm.pp[g][1];
        r.z = az + sm.pp[g][2];
        r.w = aw + sm.pp[g][3];
        *(float4*)&g_pool_part[blockIdx.x * D_ + g * 4] = r;
    }
}

__global__ __launch_bounds__(512) void finalize_kernel(float* __restrict__ out)
{
    int i = blockIdx.x * 512 + threadIdx.x;   // 0 .. B_*D_-1
    int b = i >> 8;                           // D_ == 256
    int d = i & 255;
    const float* pp = &g_pool_part[(4 * b) * D_ + d];
    float p = pp[0] + pp[D_] + pp[2 * D_] + pp[3 * D_];
    const float* ep = &g_esum_part[4 * b];
    float e = ep[0] + ep[1] + ep[2] + ep[3];
    out[i] = p / (e + 1e-7f);
}

extern "C" void kernel_launch(void* const* d_in, const int* in_sizes, int n_in,
                              void* d_out, int out_size)
{
    const float* x  = (const float*)d_in[0];
    const float* W  = (const float*)d_in[1];
    const float* bb = (const float*)d_in[2];
    const float* u  = (const float*)d_in[3];
    float* out = (float*)d_out;

    score_pool_mma<<<(B_ * T_) / ROWS, 128>>>(x, W, bb, u);
    finalize_kernel<<<(B_ * D_) / 512, 512>>>(out);
}

// round 10
// speedup vs baseline: 4.3869x; 1.3310x over previous
#include <cuda_runtime.h>
#include <cuda_bf16.h>
#include <math.h>
#include <stdint.h>

#define B_ 256
#define T_ 512
#define D_ 256
#define A_ 50
#define NP 56          // padded N (multiple of 8)
#define ROWS 128       // M tile per CTA
#define KC 32          // K chunk per pipeline stage
#define PA 40          // smem pitch in bf16 (80B rows: 16B-aligned, LDSM conflict-free)
#define NCHUNK (D_ / KC)

typedef unsigned long long u64;

__device__ __align__(16) float g_pool_part[(B_ * T_ / ROWS) * D_];
__device__ float g_esum_part[B_ * T_ / ROWS];
__device__ float g_esum[B_];
__device__ __align__(16) __nv_bfloat16 g_wtb_hi[NP * D_];   // W^T [n][k] bf16 hi
__device__ __align__(16) __nv_bfloat16 g_wtb_lo[NP * D_];   // residual lo

__device__ __forceinline__ uint32_t smem_u32(const void* p) {
    uint32_t a;
    asm("{ .reg .u64 t; cvta.to.shared.u64 t, %1; cvt.u32.u64 %0, t; }" : "=r"(a) : "l"(p));
    return a;
}
__device__ __forceinline__ void ldx4(uint32_t* r, uint32_t addr) {
    asm volatile("ldmatrix.sync.aligned.m8n8.x4.shared.b16 {%0,%1,%2,%3}, [%4];"
                 : "=r"(r[0]), "=r"(r[1]), "=r"(r[2]), "=r"(r[3]) : "r"(addr));
}
__device__ __forceinline__ void ldx2(uint32_t* r, uint32_t addr) {
    asm volatile("ldmatrix.sync.aligned.m8n8.x2.shared.b16 {%0,%1}, [%2];"
                 : "=r"(r[0]), "=r"(r[1]) : "r"(addr));
}
__device__ __forceinline__ void mma16816(float* d, const uint32_t* a, const uint32_t* b) {
    asm volatile(
        "mma.sync.aligned.m16n8k16.row.col.f32.bf16.bf16.f32 "
        "{%0,%1,%2,%3}, {%4,%5,%6,%7}, {%8,%9}, {%0,%1,%2,%3};"
        : "+f"(d[0]), "+f"(d[1]), "+f"(d[2]), "+f"(d[3])
        : "r"(a[0]), "r"(a[1]), "r"(a[2]), "r"(a[3]), "r"(b[0]), "r"(b[1]));
}
__device__ __forceinline__ uint32_t pack_bf2(float vx, float vy) {
    uint32_t p;
    asm("cvt.rn.bf16x2.f32 %0, %1, %2;" : "=r"(p) : "f"(vy), "f"(vx));
    return p;
}
__device__ __forceinline__ float tanh_fast(float v) {
    float r;
    asm("tanh.approx.f32 %0, %1;" : "=f"(r) : "f"(v));
    return r;
}
#define CPASYNC16(sm_, gm_) \
    asm volatile("cp.async.cg.shared.global [%0], [%1], 16;" :: "r"(sm_), "l"(gm_))
#define CPCOMMIT() asm volatile("cp.async.commit_group;" ::: "memory")
#define CPWAIT0()  asm volatile("cp.async.wait_group 0;"  ::: "memory")

struct __align__(16) Smem {
    __nv_bfloat16 a[2][ROWS * PA];    // 2 x 10240 B
    __nv_bfloat16 bh[2][NP * PA];     // 2 x 4480 B
    __nv_bfloat16 bl[2][NP * PA];     // 2 x 4480 B
    float sb[NP], su[NP];
    float se[ROWS];
    float wsum[4];
    float pp[64][4];
};

// Prep: W^T padded bf16 hi/lo.
__global__ __launch_bounds__(512) void prep_kernel(const float* __restrict__ W)
{
    int i = blockIdx.x * 512 + threadIdx.x;   // grid covers NP*D_ = 14336
    if (i < NP * D_) {
        int n = i / D_, k = i - n * D_;
        float w = (n < A_) ? W[k * A_ + n] : 0.0f;
        __nv_bfloat16 h = __float2bfloat16(w);
        __nv_bfloat16 l = __float2bfloat16(w - __bfloat162float(h));
        g_wtb_hi[i] = h;
        g_wtb_lo[i] = l;
    }
}

__global__ __launch_bounds__(128, 4) void score_pool_mma(
    const float* __restrict__ x, const float* __restrict__ bias,
    const float* __restrict__ u)
{
    __shared__ Smem sm;

    const int tid  = threadIdx.x;
    const int wid  = tid >> 5;
    const int lane = tid & 31;
    const int row0 = blockIdx.x * ROWS;

    if (tid < NP) {
        sm.sb[tid] = (tid < A_) ? bias[tid] : 0.0f;
        sm.su[tid] = (tid < A_) ? u[tid]    : 0.0f;
    }

    float acc[2][7][4];
    #pragma unroll
    for (int mt = 0; mt < 2; ++mt)
        #pragma unroll
        for (int nt = 0; nt < 7; ++nt)
            #pragma unroll
            for (int q = 0; q < 4; ++q) acc[mt][nt][q] = 0.0f;

    // ldmatrix per-lane address components:
    const int sub      = lane >> 3;
    const int arow_off = (sub & 1) * 8 + (lane & 7);
    const int ak_off   = (sub >> 1) * 8;
    const int bn_off   = lane & 7;
    const int bk_off   = ((lane >> 3) & 1) * 8;

    // A staging geometry: 8 float4/thread per chunk.
    const int ar  = tid >> 3;               // base row, +16 per it (8 its? no: it*16)
    const int ac4 = (tid & 7) << 2;         // col within chunk (0..28)
    // B cp.async geometry: 224 16B-ops per dtype; 2 per thread (j*128+tid < 224).
    const int bn16 = tid >> 2;              // for tid<224 slots: n = slot/4
    const int bq16 = (tid & 3) * 16;        // byte offset within 64B row chunk

    // ---- B cp.async issue helper (dtype-agnostic) ----
    auto stage_b = [&](int buf, int kc) {
        const char* ghb = (const char*)g_wtb_hi;
        const char* glb = (const char*)g_wtb_lo;
        #pragma unroll
        for (int j = 0; j < 2; ++j) {
            int s = j * 128 + tid;          // 0..255, valid < 224
            if (s < 224) {
                int n = s >> 2;
                int q = (s & 3) * 16;
                u64 goff = (u64)(n * D_ + kc * KC) * 2 + q;
                uint32_t soff = (uint32_t)(n * (PA * 2) + q);
                CPASYNC16(smem_u32(sm.bh[buf]) + soff, ghb + goff);
                CPASYNC16(smem_u32(sm.bl[buf]) + soff, glb + goff);
            }
        }
        CPCOMMIT();
    };

    float4 apref[8];
    auto ldg_a = [&](int kc) {
        #pragma unroll
        for (int it = 0; it < 8; ++it)
            apref[it] = *(const float4*)(x + (size_t)(row0 + it * 16 + ar) * D_
                                         + kc * KC + ac4);
    };
    auto sts_a = [&](int buf) {
        #pragma unroll
        for (int it = 0; it < 8; ++it) {
            uint2 p;
            p.x = pack_bf2(apref[it].x, apref[it].y);
            p.y = pack_bf2(apref[it].z, apref[it].w);
            *(uint2*)&sm.a[buf][(it * 16 + ar) * PA + ac4] = p;
        }
    };

    // ---- prologue: stage chunk 0 ----
    stage_b(0, 0);
    ldg_a(0);
    sts_a(0);
    CPWAIT0();
    __syncthreads();

    for (int kc = 0; kc < NCHUNK; ++kc) {
        const int cur = kc & 1, nxt = cur ^ 1;

        // Issue next chunk's loads first (latency hides under MMA below).
        if (kc + 1 < NCHUNK) {
            stage_b(nxt, kc + 1);
            ldg_a(kc + 1);
        }

        // ---- MMA on current buffers: 2 k16 steps, 2 chains
        const uint32_t aB  = smem_u32(sm.a[cur]);
        const uint32_t bhB = smem_u32(sm.bh[cur]);
        const uint32_t blB = smem_u32(sm.bl[cur]);
        #pragma unroll
        for (int ks = 0; ks < 2; ++ks) {
            const int k0 = ks * 16;
            uint32_t bhf[7][2], blf[7][2];
            #pragma unroll
            for (int nt = 0; nt < 7; ++nt) {
                uint32_t off = (uint32_t)(((nt * 8 + bn_off) * PA + k0 + bk_off) * 2);
                ldx2(bhf[nt], bhB + off);
                ldx2(blf[nt], blB + off);
            }
            #pragma unroll
            for (int mt = 0; mt < 2; ++mt) {
                uint32_t off = (uint32_t)(((wid * 32 + mt * 16 + arow_off) * PA
                                           + k0 + ak_off) * 2);
                uint32_t av[4];
                ldx4(av, aB + off);
                #pragma unroll
                for (int nt = 0; nt < 7; ++nt) {
                    mma16816(acc[mt][nt], av, bhf[nt]);
                    mma16816(acc[mt][nt], av, blf[nt]);
                }
            }
        }

        if (kc + 1 < NCHUNK) {
            sts_a(nxt);
            CPWAIT0();
            __syncthreads();
        }
    }

    // ---- epilogue: scores (tanh.approx + __expf; R4-validated numerics).
    #pragma unroll
    for (int mt = 0; mt < 2; ++mt) {
        float plo = 0.0f, phi = 0.0f;
        #pragma unroll
        for (int nt = 0; nt < 7; ++nt) {
            int c = nt * 8 + 2 * (lane & 3);
            plo += tanh_fast(acc[mt][nt][0] + sm.sb[c])     * sm.su[c];
            plo += tanh_fast(acc[mt][nt][1] + sm.sb[c + 1]) * sm.su[c + 1];
            phi += tanh_fast(acc[mt][nt][2] + sm.sb[c])     * sm.su[c];
            phi += tanh_fast(acc[mt][nt][3] + sm.sb[c + 1]) * sm.su[c + 1];
        }
        plo += __shfl_xor_sync(0xFFFFFFFFu, plo, 1);
        plo += __shfl_xor_sync(0xFFFFFFFFu, plo, 2);
        phi += __shfl_xor_sync(0xFFFFFFFFu, phi, 1);
        phi += __shfl_xor_sync(0xFFFFFFFFu, phi, 2);
        if ((lane & 3) == 0) {
            int r = wid * 32 + mt * 16 + (lane >> 2);
            sm.se[r]     = __expf(plo);
            sm.se[r + 8] = __expf(phi);
        }
    }
    __syncthreads();

    float e = sm.se[tid];
    float s = e;
    #pragma unroll
    for (int o = 16; o; o >>= 1) s += __shfl_xor_sync(0xFFFFFFFFu, s, o);
    if (lane == 0) sm.wsum[wid] = s;
    __syncthreads();
    if (tid == 0)
        g_esum_part[blockIdx.x] = sm.wsum[0] + sm.wsum[1] + sm.wsum[2] + sm.wsum[3];

    // ---- fused pool over this CTA's 128 rows (x L2-hot).
    const int tc = tid >> 6;
    const int g  = tid & 63;
    const float* xb = x + (size_t)(row0 + tc * 64) * D_ + g * 4;

    float ax = 0.0f, ay = 0.0f, az = 0.0f, aw = 0.0f;
    #pragma unroll 8
    for (int tt = 0; tt < 64; ++tt) {
        float w  = sm.se[tc * 64 + tt];
        float4 v = *(const float4*)(xb + (size_t)tt * D_);
        ax += v.x * w; ay += v.y * w; az += v.z * w; aw += v.w * w;
    }
    if (tc == 1) {
        sm.pp[g][0] = ax; sm.pp[g][1] = ay; sm.pp[g][2] = az; sm.pp[g][3] = aw;
    }
    __syncthreads();
    if (tc == 0) {
        float4 r;
        r.x = ax + sm.pp[g][0];
        r.y = ay + sm.pp[g][1];
        r.z = az + sm.pp[g][2];
        r.w = aw + sm.pp[g][3];
        *(float4*)&g_pool_part[blockIdx.x * D_ + g * 4] = r;
    }
}

// fin1: reduce per-CTA exp-sums to per-batch (also aligns main kernel to ncu -s 5).
__global__ __launch_bounds__(256) void esum_reduce_kernel()
{
    int b = threadIdx.x;                       // grid(1), 256 threads
    const float* ep = &g_esum_part[4 * b];
    g_esum[b] = ep[0] + ep[1] + ep[2] + ep[3];
}

__global__ __launch_bounds__(512) void finalize_kernel(float* __restrict__ out)
{
    int i = blockIdx.x * 512 + threadIdx.x;    // 0 .. B_*D_-1
    int b = i >> 8;
    int d = i & 255;
    const float* pp = &g_pool_part[(4 * b) * D_ + d];
    float p = pp[0] + pp[D_] + pp[2 * D_] + pp[3 * D_];
    out[i] = p / (g_esum[b] + 1e-7f);
}

extern "C" void kernel_launch(void* const* d_in, const int* in_sizes, int n_in,
                              void* d_out, int out_size)
{
    const float* x  = (const float*)d_in[0];
    const float* W  = (const float*)d_in[1];
    const float* bb = (const float*)d_in[2];
    const float* u  = (const float*)d_in[3];
    float* out = (float*)d_out;

    prep_kernel<<<(NP * D_ + 511) / 512, 512>>>(W);
    score_pool_mma<<<(B_ * T_) / ROWS, 128>>>(x, bb, u);
    esum_reduce_kernel<<<1, 256>>>();
    finalize_kernel<<<(B_ * D_) / 512, 512>>>(out);
}